// round 15
// baseline (speedup 1.0000x reference)
#include <cuda_runtime.h>
#include <cstdint>
#include <math.h>

// ============================================================================
// AttentionModel: QKV projection + MHA + jax-threefry dropout.
//   B=2, S=2048, D=1024, H=16, HD=64
// Round 15: attention processes TWO 64-key chunks per barrier pair
// (128-key K/V fill, halved barrier/ballot/loop overhead; S-tile stays 64
// cols so sacc stays 32 regs). Numerics and consumed dropout bits identical.
// Projection: R13 double-buffered tf32 GEMM (unchanged).
// ============================================================================

static constexpr int B_ = 2, H_ = 16, S_ = 2048, D_ = 1024, HD_ = 64;

__device__ float g_q[B_ * S_ * D_];
__device__ float g_k[B_ * S_ * D_];
__device__ float g_v[B_ * S_ * D_];

// ---------------------------------------------------------------------------
// tf32 helpers
// ---------------------------------------------------------------------------
__device__ __forceinline__ float f2tf32f(float x) {
    uint32_t r;
    asm("cvt.rna.tf32.f32 %0, %1;" : "=r"(r) : "f"(x));
    return __uint_as_float(r);
}

__device__ __forceinline__ void mma_tf32(float c[4],
                                         uint32_t a0, uint32_t a1, uint32_t a2, uint32_t a3,
                                         uint32_t b0, uint32_t b1) {
    asm volatile(
        "mma.sync.aligned.m16n8k8.row.col.f32.tf32.tf32.f32 "
        "{%0,%1,%2,%3}, {%4,%5,%6,%7}, {%8,%9}, {%0,%1,%2,%3};"
        : "+f"(c[0]), "+f"(c[1]), "+f"(c[2]), "+f"(c[3])
        : "r"(a0), "r"(a1), "r"(a2), "r"(a3), "r"(b0), "r"(b1));
}

// ---------------------------------------------------------------------------
// Threefry-2x32 (JAX partitionable) — verified exact in Round 2.
// keep(idx) <=> bits < 3865470464u (exact integer form of u < 0.9f).
// ---------------------------------------------------------------------------
struct KeyPair { unsigned a, b; };

__host__ __device__ constexpr unsigned rotlc(unsigned x, int r) {
    return (x << r) | (x >> (32 - r));
}

__host__ __device__ constexpr KeyPair threefry_block(unsigned k0, unsigned k1,
                                                     unsigned x0, unsigned x1) {
    unsigned k2 = k0 ^ k1 ^ 0x1BD11BDAu;
    x0 += k0; x1 += k1;
    const int RA[4] = {13, 15, 26, 6};
    const int RB[4] = {17, 29, 16, 24};
    for (int i = 0; i < 4; i++) { x0 += x1; x1 = rotlc(x1, RA[i]); x1 ^= x0; }
    x0 += k1; x1 += k2 + 1u;
    for (int i = 0; i < 4; i++) { x0 += x1; x1 = rotlc(x1, RB[i]); x1 ^= x0; }
    x0 += k2; x1 += k0 + 2u;
    for (int i = 0; i < 4; i++) { x0 += x1; x1 = rotlc(x1, RA[i]); x1 ^= x0; }
    x0 += k0; x1 += k1 + 3u;
    for (int i = 0; i < 4; i++) { x0 += x1; x1 = rotlc(x1, RB[i]); x1 ^= x0; }
    x0 += k1; x1 += k2 + 4u;
    for (int i = 0; i < 4; i++) { x0 += x1; x1 = rotlc(x1, RA[i]); x1 ^= x0; }
    x0 += k2; x1 += k0 + 5u;
    return {x0, x1};
}

__device__ __forceinline__ bool keep_bit(unsigned idx) {
    constexpr KeyPair FK = threefry_block(0u, 0u, 0u, 12345u);
    KeyPair r = threefry_block(FK.a, FK.b, 0u, idx);
    return (r.a ^ r.b) < 3865470464u;
}

// ---------------------------------------------------------------------------
// Rank-compacted dropout-word generation, 4 hash chains per iteration.
// ---------------------------------------------------------------------------
__device__ __forceinline__ void gen_words(int u, const int* __restrict__ Un,
                                          unsigned wrow0, unsigned cbase,
                                          int lane, int grp,
                                          unsigned& a0, unsigned& a1,
                                          unsigned& b0w, unsigned& b1w) {
    const int h = (u + 1) >> 1;
    const int rowL = lane & 15;
    const int halfS = lane >> 4;
    const int myStart = halfS ? h : 0;
    const int myCount = halfS ? (u - h) : h;
    const unsigned base = (wrow0 + (unsigned)rowL) * (unsigned)S_ + cbase;
    unsigned word = 0;
    for (int k = 0; k < h; k += 4) {
        const int c0 = (k     < myCount) ? Un[myStart + k]     : 0;
        const int c1 = (k + 1 < myCount) ? Un[myStart + k + 1] : 0;
        const int c2 = (k + 2 < myCount) ? Un[myStart + k + 2] : 0;
        const int c3 = (k + 3 < myCount) ? Un[myStart + k + 3] : 0;
        const unsigned bb0 = (unsigned)keep_bit(base + (unsigned)c0);
        const unsigned bb1 = (unsigned)keep_bit(base + (unsigned)c1);
        const unsigned bb2 = (unsigned)keep_bit(base + (unsigned)c2);
        const unsigned bb3 = (unsigned)keep_bit(base + (unsigned)c3);
        unsigned nib = bb0 | (bb1 << 1) | (bb2 << 2) | (bb3 << 3);
        const int rem = myCount - k;
        if (rem < 4) nib &= (rem <= 0) ? 0u : ((1u << rem) - 1u);
        word |= nib << k;
    }
    const unsigned other = __shfl_xor_sync(0xffffffffu, word, 16);
    const unsigned long long comb =
        (unsigned long long)word | ((unsigned long long)other << h);
    const unsigned w0 = (unsigned)comb;
    const unsigned w1 = (unsigned)(comb >> 32);
    a0  = __shfl_sync(0xffffffffu, w0, grp);
    a1  = __shfl_sync(0xffffffffu, w1, grp);
    b0w = __shfl_sync(0xffffffffu, w0, grp + 8);
    b1w = __shfl_sync(0xffffffffu, w1, grp + 8);
}

// ---------------------------------------------------------------------------
// Warp-0 mask ballot + compaction for one 64-col chunk into slot s.
// ---------------------------------------------------------------------------
__device__ __forceinline__ void ballot_chunk(const int* __restrict__ mask,
                                             int mbase, int lane,
                                             unsigned* __restrict__ Binf,
                                             int* __restrict__ Un, int s) {
    const int v0 = mask[mbase + lane];
    const int v1 = mask[mbase + 32 + lane];
    const unsigned bl0 = __ballot_sync(0xffffffffu, v0 != 0);
    const unsigned bl1 = __ballot_sync(0xffffffffu, v1 != 0);
    const int c0 = __popc(bl0);
    const int r0 = __popc(bl0 & ((1u << lane) - 1u));
    const int r1 = c0 + __popc(bl1 & ((1u << lane) - 1u));
    if (v0) Un[(s << 6) + r0] = lane;
    if (v1) Un[(s << 6) + r1] = 32 + lane;
    if (lane == 0) {
        Binf[(s << 2) + 0] = bl0;
        Binf[(s << 2) + 1] = bl1;
        Binf[(s << 2) + 2] = (unsigned)(c0 + __popc(bl1));
    }
}

// ---------------------------------------------------------------------------
// Merged projection GEMM, double-buffered (tf32 mma).  (R13, unchanged)
// ---------------------------------------------------------------------------
static constexpr int PROJ_XBUF = 128 * 36;
static constexpr int PROJ_WBUF = 64 * 36;
static constexpr int PROJ_SMEM_BYTES = 2 * (PROJ_XBUF + PROJ_WBUF) * 4;

__global__ void __launch_bounds__(256, 2) proj3_kernel(
    const float* __restrict__ Xq, const float* __restrict__ Xk, const float* __restrict__ Xv,
    const float* __restrict__ Wq, const float* __restrict__ Wk, const float* __restrict__ Wv,
    const float* __restrict__ bq, const float* __restrict__ bk, const float* __restrict__ bv) {
    extern __shared__ float psm[];
    float* Xb0 = psm;
    float* Xb1 = psm + PROJ_XBUF;
    float* Wb0 = psm + 2 * PROJ_XBUF;
    float* Wb1 = psm + 2 * PROJ_XBUF + PROJ_WBUF;

    const int bx = blockIdx.x;
    const int rsel = bx >> 9;
    const int g = bx & 511;
    const float* X    = (rsel == 0) ? Xq : (rsel == 1) ? Xk : Xv;
    const float* W    = (rsel == 0) ? Wq : (rsel == 1) ? Wk : Wv;
    const float* bias = (rsel == 0) ? bq : (rsel == 1) ? bk : bv;
    float*       Y    = (rsel == 0) ? g_q : (rsel == 1) ? g_k : g_v;

    const int m0 = (g & 31) << 7;
    const int n0 = (g >> 5) << 6;
    const int t  = threadIdx.x;
    const int lane = t & 31, w = t >> 5;
    const int grp = lane >> 2, qd = lane & 3;
    const int wm = w >> 1, wn = w & 1;
    const int frow = t >> 3;
    const int fc4  = (t & 7) << 2;

    const int xoff0 = (wm * 32 + grp) * 36 + qd;
    const int xoff1 = (wm * 32 + 16 + grp) * 36 + qd;
    const int woff  = (wn * 32 + grp) * 36 + qd;

    float acc[2][4][4];
    #pragma unroll
    for (int mt = 0; mt < 2; mt++)
        #pragma unroll
        for (int nt = 0; nt < 4; nt++)
            #pragma unroll
            for (int r = 0; r < 4; r++) acc[mt][nt][r] = 0.0f;

    float4 xr[4], wr[2];
    #pragma unroll
    for (int l = 0; l < 4; l++)
        xr[l] = *reinterpret_cast<const float4*>(&X[(size_t)(m0 + frow + (l << 5)) * D_ + fc4]);
    #pragma unroll
    for (int l = 0; l < 2; l++)
        wr[l] = *reinterpret_cast<const float4*>(&W[(size_t)(n0 + frow + (l << 5)) * D_ + fc4]);
    #pragma unroll
    for (int l = 0; l < 4; l++) {
        float* d = &Xb0[(frow + (l << 5)) * 36 + fc4];
        d[0] = f2tf32f(xr[l].x); d[1] = f2tf32f(xr[l].y);
        d[2] = f2tf32f(xr[l].z); d[3] = f2tf32f(xr[l].w);
    }
    #pragma unroll
    for (int l = 0; l < 2; l++) {
        float* d = &Wb0[(frow + (l << 5)) * 36 + fc4];
        d[0] = f2tf32f(wr[l].x); d[1] = f2tf32f(wr[l].y);
        d[2] = f2tf32f(wr[l].z); d[3] = f2tf32f(wr[l].w);
    }
    __syncthreads();

    for (int kc = 0; kc < 32; kc++) {
        if (kc + 1 < 32) {
            const int k0 = (kc + 1) << 5;
            #pragma unroll
            for (int l = 0; l < 4; l++)
                xr[l] = *reinterpret_cast<const float4*>(
                    &X[(size_t)(m0 + frow + (l << 5)) * D_ + k0 + fc4]);
            #pragma unroll
            for (int l = 0; l < 2; l++)
                wr[l] = *reinterpret_cast<const float4*>(
                    &W[(size_t)(n0 + frow + (l << 5)) * D_ + k0 + fc4]);
        }

        const float* Xc = (kc & 1) ? Xb1 : Xb0;
        const float* Wc = (kc & 1) ? Wb1 : Wb0;
        #pragma unroll
        for (int k8 = 0; k8 < 4; k8++) {
            const int kk = k8 << 3;
            uint32_t a[2][4];
            a[0][0] = __float_as_uint(Xc[xoff0 + kk]);
            a[0][1] = __float_as_uint(Xc[xoff0 + 8 * 36 + kk]);
            a[0][2] = __float_as_uint(Xc[xoff0 + kk + 4]);
            a[0][3] = __float_as_uint(Xc[xoff0 + 8 * 36 + kk + 4]);
            a[1][0] = __float_as_uint(Xc[xoff1 + kk]);
            a[1][1] = __float_as_uint(Xc[xoff1 + 8 * 36 + kk]);
            a[1][2] = __float_as_uint(Xc[xoff1 + kk + 4]);
            a[1][3] = __float_as_uint(Xc[xoff1 + 8 * 36 + kk + 4]);
            #pragma unroll
            for (int nt = 0; nt < 4; nt++) {
                uint32_t b0 = __float_as_uint(Wc[woff + nt * 8 * 36 + kk]);
                uint32_t b1 = __float_as_uint(Wc[woff + nt * 8 * 36 + kk + 4]);
                mma_tf32(acc[0][nt], a[0][0], a[0][1], a[0][2], a[0][3], b0, b1);
                mma_tf32(acc[1][nt], a[1][0], a[1][1], a[1][2], a[1][3], b0, b1);
            }
        }

        if (kc + 1 < 32) {
            float* Xn = (kc & 1) ? Xb0 : Xb1;
            float* Wn = (kc & 1) ? Wb0 : Wb1;
            #pragma unroll
            for (int l = 0; l < 4; l++) {
                float* d = &Xn[(frow + (l << 5)) * 36 + fc4];
                d[0] = f2tf32f(xr[l].x); d[1] = f2tf32f(xr[l].y);
                d[2] = f2tf32f(xr[l].z); d[3] = f2tf32f(xr[l].w);
            }
            #pragma unroll
            for (int l = 0; l < 2; l++) {
                float* d = &Wn[(frow + (l << 5)) * 36 + fc4];
                d[0] = f2tf32f(wr[l].x); d[1] = f2tf32f(wr[l].y);
                d[2] = f2tf32f(wr[l].z); d[3] = f2tf32f(wr[l].w);
            }
        }
        __syncthreads();
    }

    #pragma unroll
    for (int mt = 0; mt < 2; mt++) {
        const int r0 = m0 + wm * 32 + mt * 16 + grp;
        #pragma unroll
        for (int nt = 0; nt < 4; nt++) {
            const int c = n0 + wn * 32 + nt * 8 + (qd << 1);
            const float b0 = bias[c], b1 = bias[c + 1];
            float2 v0 = make_float2(acc[mt][nt][0] + b0, acc[mt][nt][1] + b1);
            float2 v1 = make_float2(acc[mt][nt][2] + b0, acc[mt][nt][3] + b1);
            *reinterpret_cast<float2*>(&Y[(size_t)r0 * D_ + c]) = v0;
            *reinterpret_cast<float2*>(&Y[(size_t)(r0 + 8) * D_ + c]) = v1;
        }
    }
}

// ---------------------------------------------------------------------------
// Flash attention (tf32 mma), shuffle PV, two 64-key chunks per barrier pair.
// grid (S/128, B*H), 256 thr (8 warps), 2 blocks/SM.
// smem: Qs[128][72] | Ks[128][72] | Vs[128][72] | Binf[4][4] | Un[4][64]
// ---------------------------------------------------------------------------
static constexpr int ATTN_SMEM_FLOATS = 128 * 72 + 128 * 72 + 128 * 72 + 16 + 256;
static constexpr int ATTN_SMEM_BYTES  = ATTN_SMEM_FLOATS * 4;

__global__ void __launch_bounds__(256, 2) attn_mma_kernel(const int* __restrict__ mask,
                                                          const float* __restrict__ inv_scale_p,
                                                          float* __restrict__ out) {
    extern __shared__ float sm[];
    float*    Qs = sm;
    float*    Ks = Qs + 128 * 72;
    float*    Vs = Ks + 128 * 72;
    unsigned* Binf = (unsigned*)(Vs + 128 * 72);  // [4][4]
    int*      Un   = (int*)(Binf + 16);           // [4][64]

    const int q0 = blockIdx.x << 7;
    const int bh = blockIdx.y;
    const int b  = bh >> 4;
    const int hcol = (bh & 15) << 6;
    const int t = threadIdx.x;
    const int lane = t & 31, w = t >> 5;
    const int grp = lane >> 2, qd = lane & 3;
    const int R0 = (w << 4) + grp;
    const int sw0 = R0 & 15, sw1 = (R0 + 8) & 15;
    const float scale = 1.0f / inv_scale_p[0];

    float* Q0 = &Qs[R0 * 72];
    float* Q1 = &Qs[(R0 + 8) * 72];

    const int srcA = (lane & ~3) | (qd >> 1);
    const int srcB = srcA + 2;
    const bool oddq = (qd & 1) != 0;

    const unsigned wrow0 = (unsigned)bh * (unsigned)S_ + (unsigned)(q0 + (w << 4));

    // ---- load Q tile ----
    {
        const int cq = t & 15;
        #pragma unroll
        for (int l = 0; l < 8; l++) {
            const int row = (t >> 4) + (l << 4);
            float4 v = *reinterpret_cast<const float4*>(
                &g_q[(size_t)(b * S_ + q0 + row) * D_ + hcol + (cq << 2)]);
            float* d = &Qs[row * 72 + ((cq ^ (row & 15)) << 2)];
            d[0] = f2tf32f(v.x); d[1] = f2tf32f(v.y); d[2] = f2tf32f(v.z); d[3] = f2tf32f(v.w);
        }
    }

    // ---- prologue: ballots + rank words for chunks 0,1 ----
    if (w == 0) {
        ballot_chunk(mask, b * S_,      lane, Binf, Un, 0);
        ballot_chunk(mask, b * S_ + 64, lane, Binf, Un, 1);
    }
    __syncthreads();

    unsigned cw[2][4];  // rank words for current chunk pair: [ci][ra0,ra1,rb0,rb1]
    gen_words((int)Binf[2], Un,      wrow0, 0u,  lane, grp, cw[0][0], cw[0][1], cw[0][2], cw[0][3]);
    gen_words((int)Binf[6], Un + 64, wrow0, 64u, lane, grp, cw[1][0], cw[1][1], cw[1][2], cw[1][3]);

    float oacc[8][4];
    #pragma unroll
    for (int nt = 0; nt < 8; nt++)
        #pragma unroll
        for (int r = 0; r < 4; r++) oacc[nt][r] = 0.0f;
    float mrow0 = -INFINITY, mrow1 = -INFINITY;
    float lrow0 = 0.0f, lrow1 = 0.0f;

    for (int j = 0; j < S_ / 128; j++) {
        const int kbase = j << 7;
        __syncthreads();
        // ---- fill K/V for 128 keys; warp 0 ballots chunks 2j+2, 2j+3 ----
        {
            const int cq = t & 15;
            #pragma unroll
            for (int l = 0; l < 8; l++) {
                const int row = (t >> 4) + (l << 4);
                const size_t gof = (size_t)(b * S_ + kbase + row) * D_ + hcol + (cq << 2);
                float4 kv = *reinterpret_cast<const float4*>(&g_k[gof]);
                float* dk = &Ks[row * 72 + ((cq ^ (row & 15)) << 2)];
                dk[0] = f2tf32f(kv.x); dk[1] = f2tf32f(kv.y);
                dk[2] = f2tf32f(kv.z); dk[3] = f2tf32f(kv.w);
                float4 vv = *reinterpret_cast<const float4*>(&g_v[gof]);
                float* dv = &Vs[row * 72 + (cq << 2)];
                dv[0] = f2tf32f(vv.x); dv[1] = f2tf32f(vv.y);
                dv[2] = f2tf32f(vv.z); dv[3] = f2tf32f(vv.w);
            }
            if (w == 0) {
                const int ch0 = 2 * j + 2;
                if (ch0 < 32) ballot_chunk(mask, b * S_ + (ch0 << 6), lane, Binf, Un, ch0 & 3);
                const int ch1 = 2 * j + 3;
                if (ch1 < 32) ballot_chunk(mask, b * S_ + (ch1 << 6), lane, Binf, Un, ch1 & 3);
            }
        }
        __syncthreads();

        #pragma unroll
        for (int ci = 0; ci < 2; ci++) {
            const int c = 2 * j + ci;
            const int slot = c & 3;
            const unsigned cbl0 = Binf[(slot << 2) + 0];
            const unsigned cbl1 = Binf[(slot << 2) + 1];
            const int cu0 = __popc(cbl0);
            const float* Kc = Ks + (ci << 6) * 72;
            const float* Vc = Vs + (ci << 6) * 72;

            // ---- S = Q K^T ----
            float sacc[8][4];
            #pragma unroll
            for (int nt = 0; nt < 8; nt++)
                #pragma unroll
                for (int r = 0; r < 4; r++) sacc[nt][r] = 0.0f;

            #pragma unroll
            for (int k8 = 0; k8 < 8; k8++) {
                const int cqa = 2 * k8;
                uint32_t a0 = __float_as_uint(Q0[((cqa ^ sw0) << 2) + qd]);
                uint32_t a1 = __float_as_uint(Q1[((cqa ^ sw1) << 2) + qd]);
                uint32_t a2 = __float_as_uint(Q0[(((cqa + 1) ^ sw0) << 2) + qd]);
                uint32_t a3 = __float_as_uint(Q1[(((cqa + 1) ^ sw1) << 2) + qd]);
                #pragma unroll
                for (int nt = 0; nt < 8; nt++) {
                    const int key = (nt << 3) + grp;
                    const int ksw = key & 15;
                    const float* kr = &Kc[key * 72];
                    uint32_t b0 = __float_as_uint(kr[((cqa ^ ksw) << 2) + qd]);
                    uint32_t b1 = __float_as_uint(kr[(((cqa + 1) ^ ksw) << 2) + qd]);
                    mma_tf32(sacc[nt], a0, a1, a2, a3, b0, b1);
                }
            }

            // ---- generate rank words for chunk c+2 ----
            unsigned nw0 = 0, nw1 = 0, nw2 = 0, nw3 = 0;
            const int cn = c + 2;
            if (cn < 32) {
                const int ns = cn & 3;
                gen_words((int)Binf[(ns << 2) + 2], Un + (ns << 6), wrow0,
                          (unsigned)(cn << 6), lane, grp, nw0, nw1, nw2, nw3);
            }

            // ---- mask + scale ----
            int mus0[8];
            #pragma unroll
            for (int nt = 0; nt < 8; nt++) {
                const int col = (nt << 3) + (qd << 1);
                const unsigned selw = (col < 32) ? cbl0 : cbl1;
                const int cl = col & 31;
                const int mu0 = (int)((selw >> cl) & 1u);
                const int mu1 = (int)((selw >> (cl + 1)) & 1u);
                mus0[nt] = mu0;
                sacc[nt][0] = mu0 ? sacc[nt][0] * scale : -INFINITY;
                sacc[nt][1] = mu1 ? sacc[nt][1] * scale : -INFINITY;
                sacc[nt][2] = mu0 ? sacc[nt][2] * scale : -INFINITY;
                sacc[nt][3] = mu1 ? sacc[nt][3] * scale : -INFINITY;
            }

            // ---- row max ----
            float mx0 = -INFINITY, mx1 = -INFINITY;
            #pragma unroll
            for (int nt = 0; nt < 8; nt++) {
                mx0 = fmaxf(mx0, fmaxf(sacc[nt][0], sacc[nt][1]));
                mx1 = fmaxf(mx1, fmaxf(sacc[nt][2], sacc[nt][3]));
            }
            #pragma unroll
            for (int o = 1; o < 4; o <<= 1) {
                mx0 = fmaxf(mx0, __shfl_xor_sync(0xffffffffu, mx0, o));
                mx1 = fmaxf(mx1, __shfl_xor_sync(0xffffffffu, mx1, o));
            }
            const float mn0 = fmaxf(mrow0, mx0);
            const float mn1 = fmaxf(mrow1, mx1);
            const float me0 = (mn0 == -INFINITY) ? 0.0f : mn0;
            const float me1 = (mn1 == -INFINITY) ? 0.0f : mn1;
            const float cf0 = (mrow0 == -INFINITY) ? ((mn0 == -INFINITY) ? 1.0f : 0.0f)
                                                   : __expf(mrow0 - me0);
            const float cf1 = (mrow1 == -INFINITY) ? ((mn1 == -INFINITY) ? 1.0f : 0.0f)
                                                   : __expf(mrow1 - me1);
            mrow0 = mn0;
            mrow1 = mn1;
            #pragma unroll
            for (int nt = 0; nt < 8; nt++) {
                oacc[nt][0] *= cf0; oacc[nt][1] *= cf0;
                oacc[nt][2] *= cf1; oacc[nt][3] *= cf1;
            }

            // ---- fused: exp, dropout, C->A shuffle, PV mma ----
            float rs0 = 0.0f, rs1 = 0.0f;
            #pragma unroll
            for (int nt = 0; nt < 8; nt++) {
                const int col = (nt << 3) + (qd << 1);
                const int cl = col & 31;
                const unsigned pmsk = (1u << cl) - 1u;
                const int rank0 = (col < 32) ? __popc(cbl0 & pmsk)
                                             : (cu0 + __popc(cbl1 & pmsk));
                const int rank1 = rank0 + mus0[nt];
                const unsigned wA0 = (rank0 < 32) ? cw[ci][0] : cw[ci][1];
                const unsigned wA1 = (rank1 < 32) ? cw[ci][0] : cw[ci][1];
                const unsigned wB0 = (rank0 < 32) ? cw[ci][2] : cw[ci][3];
                const unsigned wB1 = (rank1 < 32) ? cw[ci][2] : cw[ci][3];
                const unsigned k00 = (wA0 >> (rank0 & 31)) & 1u;
                const unsigned k01 = (wA1 >> (rank1 & 31)) & 1u;
                const unsigned k10 = (wB0 >> (rank0 & 31)) & 1u;
                const unsigned k11 = (wB1 >> (rank1 & 31)) & 1u;
                const float p00 = __expf(sacc[nt][0] - me0);
                const float p01 = __expf(sacc[nt][1] - me0);
                const float p10 = __expf(sacc[nt][2] - me1);
                const float p11 = __expf(sacc[nt][3] - me1);
                rs0 += p00 + p01;
                rs1 += p10 + p11;
                const float d00 = k00 ? p00 * (1.0f / 0.9f) : 0.0f;
                const float d01 = k01 ? p01 * (1.0f / 0.9f) : 0.0f;
                const float d10 = k10 ? p10 * (1.0f / 0.9f) : 0.0f;
                const float d11 = k11 ? p11 * (1.0f / 0.9f) : 0.0f;

                const float e00 = __shfl_sync(0xffffffffu, d00, srcA);
                const float e01 = __shfl_sync(0xffffffffu, d01, srcA);
                const float e02 = __shfl_sync(0xffffffffu, d00, srcB);
                const float e03 = __shfl_sync(0xffffffffu, d01, srcB);
                const float f00 = __shfl_sync(0xffffffffu, d10, srcA);
                const float f01 = __shfl_sync(0xffffffffu, d11, srcA);
                const float f02 = __shfl_sync(0xffffffffu, d10, srcB);
                const float f03 = __shfl_sync(0xffffffffu, d11, srcB);
                const uint32_t pa0 = __float_as_uint(f2tf32f(oddq ? e01 : e00));
                const uint32_t pa1 = __float_as_uint(f2tf32f(oddq ? f01 : f00));
                const uint32_t pa2 = __float_as_uint(f2tf32f(oddq ? e03 : e02));
                const uint32_t pa3 = __float_as_uint(f2tf32f(oddq ? f03 : f02));

                const float* v0 = &Vc[((nt << 3) + qd) * 72 + grp];
                #pragma unroll
                for (int dt = 0; dt < 8; dt++) {
                    uint32_t b0 = __float_as_uint(v0[dt << 3]);
                    uint32_t b1 = __float_as_uint(v0[4 * 72 + (dt << 3)]);
                    mma_tf32(oacc[dt], pa0, pa1, pa2, pa3, b0, b1);
                }
            }
            #pragma unroll
            for (int o = 1; o < 4; o <<= 1) {
                rs0 += __shfl_xor_sync(0xffffffffu, rs0, o);
                rs1 += __shfl_xor_sync(0xffffffffu, rs1, o);
            }
            lrow0 = lrow0 * cf0 + rs0;
            lrow1 = lrow1 * cf1 + rs1;

            cw[ci][0] = nw0; cw[ci][1] = nw1; cw[ci][2] = nw2; cw[ci][3] = nw3;
        }
    }

    const float il0 = 1.0f / lrow0;
    const float il1 = 1.0f / lrow1;
    const size_t g0 = ((size_t)bh * S_ + q0 + R0) * HD_;
    const size_t g1 = ((size_t)bh * S_ + q0 + R0 + 8) * HD_;
    #pragma unroll
    for (int nt = 0; nt < 8; nt++) {
        const int col = (nt << 3) + (qd << 1);
        *reinterpret_cast<float2*>(&out[g0 + col]) =
            make_float2(oacc[nt][0] * il0, oacc[nt][1] * il0);
        *reinterpret_cast<float2*>(&out[g1 + col]) =
            make_float2(oacc[nt][2] * il1, oacc[nt][3] * il1);
    }
}

// ---------------------------------------------------------------------------
extern "C" void kernel_launch(void* const* d_in, const int* in_sizes, int n_in,
                              void* d_out, int out_size) {
    (void)in_sizes; (void)n_in; (void)out_size;
    const float* query = (const float*)d_in[0];
    const float* key   = (const float*)d_in[1];
    const float* value = (const float*)d_in[2];
    const int*   mask  = (const int*)d_in[3];
    const float* invsc = (const float*)d_in[4];
    const float* Wq    = (const float*)d_in[5];
    const float* bq    = (const float*)d_in[6];
    const float* Wk    = (const float*)d_in[7];
    const float* bk    = (const float*)d_in[8];
    const float* Wv    = (const float*)d_in[9];
    const float* bv    = (const float*)d_in[10];
    float*       out   = (float*)d_out;

    cudaFuncSetAttribute(proj3_kernel, cudaFuncAttributeMaxDynamicSharedMemorySize,
                         PROJ_SMEM_BYTES);
    proj3_kernel<<<1536, 256, PROJ_SMEM_BYTES>>>(query, key, value,
                                                 Wq, Wk, Wv, bq, bk, bv);

    cudaFuncSetAttribute(attn_mma_kernel, cudaFuncAttributeMaxDynamicSharedMemorySize,
                         ATTN_SMEM_BYTES);
    dim3 ag(S_ / 128, B_ * H_);
    attn_mma_kernel<<<ag, 256, ATTN_SMEM_BYTES>>>(mask, invsc, out);
}

// round 17
// speedup vs baseline: 1.0179x; 1.0179x over previous
#include <cuda_runtime.h>
#include <cstdint>
#include <math.h>

// ============================================================================
// AttentionModel: QKV projection + MHA + jax-threefry dropout.
//   B=2, S=2048, D=1024, H=16, HD=64
// Round 16 design (resubmit; prior run died to container infra):
// R14 attention (64-key tiles, shuffle PV) + double-buffered K/V smem with
// ONE __syncthreads per tile (was 2); ballot metadata in mod-4 slots for
// race-freedom. Register footprint identical to R14.
// Projection: R13 double-buffered tf32 GEMM (unchanged).
// ============================================================================

static constexpr int B_ = 2, H_ = 16, S_ = 2048, D_ = 1024, HD_ = 64;

__device__ float g_q[B_ * S_ * D_];
__device__ float g_k[B_ * S_ * D_];
__device__ float g_v[B_ * S_ * D_];

// ---------------------------------------------------------------------------
// tf32 helpers
// ---------------------------------------------------------------------------
__device__ __forceinline__ float f2tf32f(float x) {
    uint32_t r;
    asm("cvt.rna.tf32.f32 %0, %1;" : "=r"(r) : "f"(x));
    return __uint_as_float(r);
}

__device__ __forceinline__ void mma_tf32(float c[4],
                                         uint32_t a0, uint32_t a1, uint32_t a2, uint32_t a3,
                                         uint32_t b0, uint32_t b1) {
    asm volatile(
        "mma.sync.aligned.m16n8k8.row.col.f32.tf32.tf32.f32 "
        "{%0,%1,%2,%3}, {%4,%5,%6,%7}, {%8,%9}, {%0,%1,%2,%3};"
        : "+f"(c[0]), "+f"(c[1]), "+f"(c[2]), "+f"(c[3])
        : "r"(a0), "r"(a1), "r"(a2), "r"(a3), "r"(b0), "r"(b1));
}

// ---------------------------------------------------------------------------
// Threefry-2x32 (JAX partitionable) — verified exact in Round 2.
// keep(idx) <=> bits < 3865470464u (exact integer form of u < 0.9f).
// ---------------------------------------------------------------------------
struct KeyPair { unsigned a, b; };

__host__ __device__ constexpr unsigned rotlc(unsigned x, int r) {
    return (x << r) | (x >> (32 - r));
}

__host__ __device__ constexpr KeyPair threefry_block(unsigned k0, unsigned k1,
                                                     unsigned x0, unsigned x1) {
    unsigned k2 = k0 ^ k1 ^ 0x1BD11BDAu;
    x0 += k0; x1 += k1;
    const int RA[4] = {13, 15, 26, 6};
    const int RB[4] = {17, 29, 16, 24};
    for (int i = 0; i < 4; i++) { x0 += x1; x1 = rotlc(x1, RA[i]); x1 ^= x0; }
    x0 += k1; x1 += k2 + 1u;
    for (int i = 0; i < 4; i++) { x0 += x1; x1 = rotlc(x1, RB[i]); x1 ^= x0; }
    x0 += k2; x1 += k0 + 2u;
    for (int i = 0; i < 4; i++) { x0 += x1; x1 = rotlc(x1, RA[i]); x1 ^= x0; }
    x0 += k0; x1 += k1 + 3u;
    for (int i = 0; i < 4; i++) { x0 += x1; x1 = rotlc(x1, RB[i]); x1 ^= x0; }
    x0 += k1; x1 += k2 + 4u;
    for (int i = 0; i < 4; i++) { x0 += x1; x1 = rotlc(x1, RA[i]); x1 ^= x0; }
    x0 += k2; x1 += k0 + 5u;
    return {x0, x1};
}

__device__ __forceinline__ bool keep_bit(unsigned idx) {
    constexpr KeyPair FK = threefry_block(0u, 0u, 0u, 12345u);
    KeyPair r = threefry_block(FK.a, FK.b, 0u, idx);
    return (r.a ^ r.b) < 3865470464u;
}

// ---------------------------------------------------------------------------
// Rank-compacted dropout-word generation, 4 hash chains per iteration.
// ---------------------------------------------------------------------------
__device__ __forceinline__ void gen_words(int u, const int* __restrict__ Un,
                                          unsigned wrow0, unsigned cbase,
                                          int lane, int grp,
                                          unsigned& a0, unsigned& a1,
                                          unsigned& b0w, unsigned& b1w) {
    const int h = (u + 1) >> 1;
    const int rowL = lane & 15;
    const int halfS = lane >> 4;
    const int myStart = halfS ? h : 0;
    const int myCount = halfS ? (u - h) : h;
    const unsigned base = (wrow0 + (unsigned)rowL) * (unsigned)S_ + cbase;
    unsigned word = 0;
    for (int k = 0; k < h; k += 4) {
        const int c0 = (k     < myCount) ? Un[myStart + k]     : 0;
        const int c1 = (k + 1 < myCount) ? Un[myStart + k + 1] : 0;
        const int c2 = (k + 2 < myCount) ? Un[myStart + k + 2] : 0;
        const int c3 = (k + 3 < myCount) ? Un[myStart + k + 3] : 0;
        const unsigned bb0 = (unsigned)keep_bit(base + (unsigned)c0);
        const unsigned bb1 = (unsigned)keep_bit(base + (unsigned)c1);
        const unsigned bb2 = (unsigned)keep_bit(base + (unsigned)c2);
        const unsigned bb3 = (unsigned)keep_bit(base + (unsigned)c3);
        unsigned nib = bb0 | (bb1 << 1) | (bb2 << 2) | (bb3 << 3);
        const int rem = myCount - k;
        if (rem < 4) nib &= (rem <= 0) ? 0u : ((1u << rem) - 1u);
        word |= nib << k;
    }
    const unsigned other = __shfl_xor_sync(0xffffffffu, word, 16);
    const unsigned long long comb =
        (unsigned long long)word | ((unsigned long long)other << h);
    const unsigned w0 = (unsigned)comb;
    const unsigned w1 = (unsigned)(comb >> 32);
    a0  = __shfl_sync(0xffffffffu, w0, grp);
    a1  = __shfl_sync(0xffffffffu, w1, grp);
    b0w = __shfl_sync(0xffffffffu, w0, grp + 8);
    b1w = __shfl_sync(0xffffffffu, w1, grp + 8);
}

// ---------------------------------------------------------------------------
// Warp-0 mask ballot + compaction for one 64-col tile into mod-4 slot s.
// ---------------------------------------------------------------------------
__device__ __forceinline__ void ballot_chunk(const int* __restrict__ mask,
                                             int mbase, int lane,
                                             unsigned* __restrict__ Binf,
                                             int* __restrict__ Un, int s) {
    const int v0 = mask[mbase + lane];
    const int v1 = mask[mbase + 32 + lane];
    const unsigned bl0 = __ballot_sync(0xffffffffu, v0 != 0);
    const unsigned bl1 = __ballot_sync(0xffffffffu, v1 != 0);
    const int c0 = __popc(bl0);
    const int r0 = __popc(bl0 & ((1u << lane) - 1u));
    const int r1 = c0 + __popc(bl1 & ((1u << lane) - 1u));
    if (v0) Un[(s << 6) + r0] = lane;
    if (v1) Un[(s << 6) + r1] = 32 + lane;
    if (lane == 0) {
        Binf[(s << 2) + 0] = bl0;
        Binf[(s << 2) + 1] = bl1;
        Binf[(s << 2) + 2] = (unsigned)(c0 + __popc(bl1));
    }
}

// ---------------------------------------------------------------------------
// Merged projection GEMM, double-buffered (tf32 mma).  (R13, unchanged)
// ---------------------------------------------------------------------------
static constexpr int PROJ_XBUF = 128 * 36;
static constexpr int PROJ_WBUF = 64 * 36;
static constexpr int PROJ_SMEM_BYTES = 2 * (PROJ_XBUF + PROJ_WBUF) * 4;

__global__ void __launch_bounds__(256, 2) proj3_kernel(
    const float* __restrict__ Xq, const float* __restrict__ Xk, const float* __restrict__ Xv,
    const float* __restrict__ Wq, const float* __restrict__ Wk, const float* __restrict__ Wv,
    const float* __restrict__ bq, const float* __restrict__ bk, const float* __restrict__ bv) {
    extern __shared__ float psm[];
    float* Xb0 = psm;
    float* Xb1 = psm + PROJ_XBUF;
    float* Wb0 = psm + 2 * PROJ_XBUF;
    float* Wb1 = psm + 2 * PROJ_XBUF + PROJ_WBUF;

    const int bx = blockIdx.x;
    const int rsel = bx >> 9;
    const int g = bx & 511;
    const float* X    = (rsel == 0) ? Xq : (rsel == 1) ? Xk : Xv;
    const float* W    = (rsel == 0) ? Wq : (rsel == 1) ? Wk : Wv;
    const float* bias = (rsel == 0) ? bq : (rsel == 1) ? bk : bv;
    float*       Y    = (rsel == 0) ? g_q : (rsel == 1) ? g_k : g_v;

    const int m0 = (g & 31) << 7;
    const int n0 = (g >> 5) << 6;
    const int t  = threadIdx.x;
    const int lane = t & 31, w = t >> 5;
    const int grp = lane >> 2, qd = lane & 3;
    const int wm = w >> 1, wn = w & 1;
    const int frow = t >> 3;
    const int fc4  = (t & 7) << 2;

    const int xoff0 = (wm * 32 + grp) * 36 + qd;
    const int xoff1 = (wm * 32 + 16 + grp) * 36 + qd;
    const int woff  = (wn * 32 + grp) * 36 + qd;

    float acc[2][4][4];
    #pragma unroll
    for (int mt = 0; mt < 2; mt++)
        #pragma unroll
        for (int nt = 0; nt < 4; nt++)
            #pragma unroll
            for (int r = 0; r < 4; r++) acc[mt][nt][r] = 0.0f;

    float4 xr[4], wr[2];
    #pragma unroll
    for (int l = 0; l < 4; l++)
        xr[l] = *reinterpret_cast<const float4*>(&X[(size_t)(m0 + frow + (l << 5)) * D_ + fc4]);
    #pragma unroll
    for (int l = 0; l < 2; l++)
        wr[l] = *reinterpret_cast<const float4*>(&W[(size_t)(n0 + frow + (l << 5)) * D_ + fc4]);
    #pragma unroll
    for (int l = 0; l < 4; l++) {
        float* d = &Xb0[(frow + (l << 5)) * 36 + fc4];
        d[0] = f2tf32f(xr[l].x); d[1] = f2tf32f(xr[l].y);
        d[2] = f2tf32f(xr[l].z); d[3] = f2tf32f(xr[l].w);
    }
    #pragma unroll
    for (int l = 0; l < 2; l++) {
        float* d = &Wb0[(frow + (l << 5)) * 36 + fc4];
        d[0] = f2tf32f(wr[l].x); d[1] = f2tf32f(wr[l].y);
        d[2] = f2tf32f(wr[l].z); d[3] = f2tf32f(wr[l].w);
    }
    __syncthreads();

    for (int kc = 0; kc < 32; kc++) {
        if (kc + 1 < 32) {
            const int k0 = (kc + 1) << 5;
            #pragma unroll
            for (int l = 0; l < 4; l++)
                xr[l] = *reinterpret_cast<const float4*>(
                    &X[(size_t)(m0 + frow + (l << 5)) * D_ + k0 + fc4]);
            #pragma unroll
            for (int l = 0; l < 2; l++)
                wr[l] = *reinterpret_cast<const float4*>(
                    &W[(size_t)(n0 + frow + (l << 5)) * D_ + k0 + fc4]);
        }

        const float* Xc = (kc & 1) ? Xb1 : Xb0;
        const float* Wc = (kc & 1) ? Wb1 : Wb0;
        #pragma unroll
        for (int k8 = 0; k8 < 4; k8++) {
            const int kk = k8 << 3;
            uint32_t a[2][4];
            a[0][0] = __float_as_uint(Xc[xoff0 + kk]);
            a[0][1] = __float_as_uint(Xc[xoff0 + 8 * 36 + kk]);
            a[0][2] = __float_as_uint(Xc[xoff0 + kk + 4]);
            a[0][3] = __float_as_uint(Xc[xoff0 + 8 * 36 + kk + 4]);
            a[1][0] = __float_as_uint(Xc[xoff1 + kk]);
            a[1][1] = __float_as_uint(Xc[xoff1 + 8 * 36 + kk]);
            a[1][2] = __float_as_uint(Xc[xoff1 + kk + 4]);
            a[1][3] = __float_as_uint(Xc[xoff1 + 8 * 36 + kk + 4]);
            #pragma unroll
            for (int nt = 0; nt < 4; nt++) {
                uint32_t b0 = __float_as_uint(Wc[woff + nt * 8 * 36 + kk]);
                uint32_t b1 = __float_as_uint(Wc[woff + nt * 8 * 36 + kk + 4]);
                mma_tf32(acc[0][nt], a[0][0], a[0][1], a[0][2], a[0][3], b0, b1);
                mma_tf32(acc[1][nt], a[1][0], a[1][1], a[1][2], a[1][3], b0, b1);
            }
        }

        if (kc + 1 < 32) {
            float* Xn = (kc & 1) ? Xb0 : Xb1;
            float* Wn = (kc & 1) ? Wb0 : Wb1;
            #pragma unroll
            for (int l = 0; l < 4; l++) {
                float* d = &Xn[(frow + (l << 5)) * 36 + fc4];
                d[0] = f2tf32f(xr[l].x); d[1] = f2tf32f(xr[l].y);
                d[2] = f2tf32f(xr[l].z); d[3] = f2tf32f(xr[l].w);
            }
            #pragma unroll
            for (int l = 0; l < 2; l++) {
                float* d = &Wn[(frow + (l << 5)) * 36 + fc4];
                d[0] = f2tf32f(wr[l].x); d[1] = f2tf32f(wr[l].y);
                d[2] = f2tf32f(wr[l].z); d[3] = f2tf32f(wr[l].w);
            }
        }
        __syncthreads();
    }

    #pragma unroll
    for (int mt = 0; mt < 2; mt++) {
        const int r0 = m0 + wm * 32 + mt * 16 + grp;
        #pragma unroll
        for (int nt = 0; nt < 4; nt++) {
            const int c = n0 + wn * 32 + nt * 8 + (qd << 1);
            const float b0 = bias[c], b1 = bias[c + 1];
            float2 v0 = make_float2(acc[mt][nt][0] + b0, acc[mt][nt][1] + b1);
            float2 v1 = make_float2(acc[mt][nt][2] + b0, acc[mt][nt][3] + b1);
            *reinterpret_cast<float2*>(&Y[(size_t)r0 * D_ + c]) = v0;
            *reinterpret_cast<float2*>(&Y[(size_t)(r0 + 8) * D_ + c]) = v1;
        }
    }
}

// ---------------------------------------------------------------------------
// Flash attention (tf32 mma), shuffle PV, double-buffered K/V, 1 sync/tile.
// grid (S/128, B*H), 256 thr (8 warps), 2 blocks/SM.
// smem: Qs[128][72] | Ks[2][64][72] | Vs[2][64][72] | Binf[4][4] | Un[4][64]
// ---------------------------------------------------------------------------
static constexpr int ATTN_SMEM_FLOATS = 128 * 72 + 2 * 64 * 72 + 2 * 64 * 72 + 16 + 256;
static constexpr int ATTN_SMEM_BYTES  = ATTN_SMEM_FLOATS * 4;

__global__ void __launch_bounds__(256, 2) attn_mma_kernel(const int* __restrict__ mask,
                                                          const float* __restrict__ inv_scale_p,
                                                          float* __restrict__ out) {
    extern __shared__ float sm[];
    float*    Qs = sm;
    float*    Ks = Qs + 128 * 72;               // 2 buffers of 64x72
    float*    Vs = Ks + 2 * 64 * 72;            // 2 buffers of 64x72
    unsigned* Binf = (unsigned*)(Vs + 2 * 64 * 72);  // [4][4], mod-4 slots
    int*      Un   = (int*)(Binf + 16);              // [4][64]

    const int q0 = blockIdx.x << 7;
    const int bh = blockIdx.y;
    const int b  = bh >> 4;
    const int hcol = (bh & 15) << 6;
    const int t = threadIdx.x;
    const int lane = t & 31, w = t >> 5;
    const int grp = lane >> 2, qd = lane & 3;
    const int R0 = (w << 4) + grp;
    const int sw0 = R0 & 15, sw1 = (R0 + 8) & 15;
    const float scale = 1.0f / inv_scale_p[0];

    float* Q0 = &Qs[R0 * 72];
    float* Q1 = &Qs[(R0 + 8) * 72];

    const int srcA = (lane & ~3) | (qd >> 1);
    const int srcB = srcA + 2;
    const bool oddq = (qd & 1) != 0;

    const unsigned wrow0 = (unsigned)bh * (unsigned)S_ + (unsigned)(q0 + (w << 4));

    // ---- load Q tile ----
    {
        const int cq = t & 15;
        #pragma unroll
        for (int l = 0; l < 8; l++) {
            const int row = (t >> 4) + (l << 4);
            float4 v = *reinterpret_cast<const float4*>(
                &g_q[(size_t)(b * S_ + q0 + row) * D_ + hcol + (cq << 2)]);
            float* d = &Qs[row * 72 + ((cq ^ (row & 15)) << 2)];
            d[0] = f2tf32f(v.x); d[1] = f2tf32f(v.y); d[2] = f2tf32f(v.z); d[3] = f2tf32f(v.w);
        }
    }

    // ---- prologue: ballot tile 0, then its rank words ----
    if (w == 0) ballot_chunk(mask, b * S_, lane, Binf, Un, 0);
    __syncthreads();

    unsigned ra0, ra1, rb0w, rb1w;
    gen_words((int)Binf[2], Un, wrow0, 0u, lane, grp, ra0, ra1, rb0w, rb1w);

    float oacc[8][4];
    #pragma unroll
    for (int nt = 0; nt < 8; nt++)
        #pragma unroll
        for (int r = 0; r < 4; r++) oacc[nt][r] = 0.0f;
    float mrow0 = -INFINITY, mrow1 = -INFINITY;
    float lrow0 = 0.0f, lrow1 = 0.0f;

    for (int kt = 0; kt < S_ / 64; kt++) {
        const int kbase = kt << 6;
        float* Kb = Ks + (kt & 1) * (64 * 72);
        float* Vb = Vs + (kt & 1) * (64 * 72);

        // ---- fill buf[kt&1] with tile kt; warp 0 ballots tile kt+1 ----
        {
            const int cq = t & 15;
            #pragma unroll
            for (int l = 0; l < 4; l++) {
                const int row = (t >> 4) + (l << 4);
                const size_t gof = (size_t)(b * S_ + kbase + row) * D_ + hcol + (cq << 2);
                float4 kv = *reinterpret_cast<const float4*>(&g_k[gof]);
                float* dk = &Kb[row * 72 + ((cq ^ (row & 15)) << 2)];
                dk[0] = f2tf32f(kv.x); dk[1] = f2tf32f(kv.y);
                dk[2] = f2tf32f(kv.z); dk[3] = f2tf32f(kv.w);
                float4 vv = *reinterpret_cast<const float4*>(&g_v[gof]);
                float* dv = &Vb[row * 72 + (cq << 2)];
                dv[0] = f2tf32f(vv.x); dv[1] = f2tf32f(vv.y);
                dv[2] = f2tf32f(vv.z); dv[3] = f2tf32f(vv.w);
            }
            if (w == 0 && kt + 1 < S_ / 64)
                ballot_chunk(mask, b * S_ + ((kt + 1) << 6), lane, Binf, Un, (kt + 1) & 3);
        }
        __syncthreads();  // the only barrier per tile

        const int slot = kt & 3;
        const unsigned cbl0 = Binf[(slot << 2) + 0];
        const unsigned cbl1 = Binf[(slot << 2) + 1];
        const int cu0 = __popc(cbl0);

        // ---- S = Q K^T ----
        float sacc[8][4];
        #pragma unroll
        for (int nt = 0; nt < 8; nt++)
            #pragma unroll
            for (int r = 0; r < 4; r++) sacc[nt][r] = 0.0f;

        #pragma unroll
        for (int k8 = 0; k8 < 8; k8++) {
            const int cqa = 2 * k8;
            uint32_t a0 = __float_as_uint(Q0[((cqa ^ sw0) << 2) + qd]);
            uint32_t a1 = __float_as_uint(Q1[((cqa ^ sw1) << 2) + qd]);
            uint32_t a2 = __float_as_uint(Q0[(((cqa + 1) ^ sw0) << 2) + qd]);
            uint32_t a3 = __float_as_uint(Q1[(((cqa + 1) ^ sw1) << 2) + qd]);
            #pragma unroll
            for (int nt = 0; nt < 8; nt++) {
                const int key = (nt << 3) + grp;
                const int ksw = key & 15;
                const float* kr = &Kb[key * 72];
                uint32_t b0 = __float_as_uint(kr[((cqa ^ ksw) << 2) + qd]);
                uint32_t b1 = __float_as_uint(kr[(((cqa + 1) ^ ksw) << 2) + qd]);
                mma_tf32(sacc[nt], a0, a1, a2, a3, b0, b1);
            }
        }

        // ---- generate NEXT tile's rank words (slot (kt+1)&3) ----
        unsigned na0 = 0, na1 = 0, nb0w = 0, nb1w = 0;
        if (kt + 1 < S_ / 64) {
            const int ns = (kt + 1) & 3;
            gen_words((int)Binf[(ns << 2) + 2], Un + (ns << 6), wrow0,
                      (unsigned)((kt + 1) << 6), lane, grp, na0, na1, nb0w, nb1w);
        }

        // ---- mask + scale ----
        int mus0[8];
        #pragma unroll
        for (int nt = 0; nt < 8; nt++) {
            const int col = (nt << 3) + (qd << 1);
            const unsigned selw = (col < 32) ? cbl0 : cbl1;
            const int cl = col & 31;
            const int mu0 = (int)((selw >> cl) & 1u);
            const int mu1 = (int)((selw >> (cl + 1)) & 1u);
            mus0[nt] = mu0;
            sacc[nt][0] = mu0 ? sacc[nt][0] * scale : -INFINITY;
            sacc[nt][1] = mu1 ? sacc[nt][1] * scale : -INFINITY;
            sacc[nt][2] = mu0 ? sacc[nt][2] * scale : -INFINITY;
            sacc[nt][3] = mu1 ? sacc[nt][3] * scale : -INFINITY;
        }

        // ---- row max ----
        float mx0 = -INFINITY, mx1 = -INFINITY;
        #pragma unroll
        for (int nt = 0; nt < 8; nt++) {
            mx0 = fmaxf(mx0, fmaxf(sacc[nt][0], sacc[nt][1]));
            mx1 = fmaxf(mx1, fmaxf(sacc[nt][2], sacc[nt][3]));
        }
        #pragma unroll
        for (int o = 1; o < 4; o <<= 1) {
            mx0 = fmaxf(mx0, __shfl_xor_sync(0xffffffffu, mx0, o));
            mx1 = fmaxf(mx1, __shfl_xor_sync(0xffffffffu, mx1, o));
        }
        const float mn0 = fmaxf(mrow0, mx0);
        const float mn1 = fmaxf(mrow1, mx1);
        const float me0 = (mn0 == -INFINITY) ? 0.0f : mn0;
        const float me1 = (mn1 == -INFINITY) ? 0.0f : mn1;
        const float cf0 = (mrow0 == -INFINITY) ? ((mn0 == -INFINITY) ? 1.0f : 0.0f)
                                               : __expf(mrow0 - me0);
        const float cf1 = (mrow1 == -INFINITY) ? ((mn1 == -INFINITY) ? 1.0f : 0.0f)
                                               : __expf(mrow1 - me1);
        mrow0 = mn0;
        mrow1 = mn1;
        #pragma unroll
        for (int nt = 0; nt < 8; nt++) {
            oacc[nt][0] *= cf0; oacc[nt][1] *= cf0;
            oacc[nt][2] *= cf1; oacc[nt][3] *= cf1;
        }

        // ---- fused: exp, dropout, C->A shuffle, PV mma ----
        float rs0 = 0.0f, rs1 = 0.0f;
        #pragma unroll
        for (int nt = 0; nt < 8; nt++) {
            const int col = (nt << 3) + (qd << 1);
            const int cl = col & 31;
            const unsigned pmsk = (1u << cl) - 1u;
            const int rank0 = (col < 32) ? __popc(cbl0 & pmsk)
                                         : (cu0 + __popc(cbl1 & pmsk));
            const int rank1 = rank0 + mus0[nt];
            const unsigned wA0 = (rank0 < 32) ? ra0 : ra1;
            const unsigned wA1 = (rank1 < 32) ? ra0 : ra1;
            const unsigned wB0 = (rank0 < 32) ? rb0w : rb1w;
            const unsigned wB1 = (rank1 < 32) ? rb0w : rb1w;
            const unsigned k00 = (wA0 >> (rank0 & 31)) & 1u;
            const unsigned k01 = (wA1 >> (rank1 & 31)) & 1u;
            const unsigned k10 = (wB0 >> (rank0 & 31)) & 1u;
            const unsigned k11 = (wB1 >> (rank1 & 31)) & 1u;
            const float p00 = __expf(sacc[nt][0] - me0);
            const float p01 = __expf(sacc[nt][1] - me0);
            const float p10 = __expf(sacc[nt][2] - me1);
            const float p11 = __expf(sacc[nt][3] - me1);
            rs0 += p00 + p01;
            rs1 += p10 + p11;
            const float d00 = k00 ? p00 * (1.0f / 0.9f) : 0.0f;
            const float d01 = k01 ? p01 * (1.0f / 0.9f) : 0.0f;
            const float d10 = k10 ? p10 * (1.0f / 0.9f) : 0.0f;
            const float d11 = k11 ? p11 * (1.0f / 0.9f) : 0.0f;

            const float e00 = __shfl_sync(0xffffffffu, d00, srcA);
            const float e01 = __shfl_sync(0xffffffffu, d01, srcA);
            const float e02 = __shfl_sync(0xffffffffu, d00, srcB);
            const float e03 = __shfl_sync(0xffffffffu, d01, srcB);
            const float f00 = __shfl_sync(0xffffffffu, d10, srcA);
            const float f01 = __shfl_sync(0xffffffffu, d11, srcA);
            const float f02 = __shfl_sync(0xffffffffu, d10, srcB);
            const float f03 = __shfl_sync(0xffffffffu, d11, srcB);
            const uint32_t pa0 = __float_as_uint(f2tf32f(oddq ? e01 : e00));
            const uint32_t pa1 = __float_as_uint(f2tf32f(oddq ? f01 : f00));
            const uint32_t pa2 = __float_as_uint(f2tf32f(oddq ? e03 : e02));
            const uint32_t pa3 = __float_as_uint(f2tf32f(oddq ? f03 : f02));

            const float* v0 = &Vb[((nt << 3) + qd) * 72 + grp];
            #pragma unroll
            for (int dt = 0; dt < 8; dt++) {
                uint32_t b0 = __float_as_uint(v0[dt << 3]);
                uint32_t b1 = __float_as_uint(v0[4 * 72 + (dt << 3)]);
                mma_tf32(oacc[dt], pa0, pa1, pa2, pa3, b0, b1);
            }
        }
        #pragma unroll
        for (int o = 1; o < 4; o <<= 1) {
            rs0 += __shfl_xor_sync(0xffffffffu, rs0, o);
            rs1 += __shfl_xor_sync(0xffffffffu, rs1, o);
        }
        lrow0 = lrow0 * cf0 + rs0;
        lrow1 = lrow1 * cf1 + rs1;

        ra0 = na0; ra1 = na1; rb0w = nb0w; rb1w = nb1w;
    }

    const float il0 = 1.0f / lrow0;
    const float il1 = 1.0f / lrow1;
    const size_t g0 = ((size_t)bh * S_ + q0 + R0) * HD_;
    const size_t g1 = ((size_t)bh * S_ + q0 + R0 + 8) * HD_;
    #pragma unroll
    for (int nt = 0; nt < 8; nt++) {
        const int col = (nt << 3) + (qd << 1);
        *reinterpret_cast<float2*>(&out[g0 + col]) =
            make_float2(oacc[nt][0] * il0, oacc[nt][1] * il0);
        *reinterpret_cast<float2*>(&out[g1 + col]) =
            make_float2(oacc[nt][2] * il1, oacc[nt][3] * il1);
    }
}

// ---------------------------------------------------------------------------
extern "C" void kernel_launch(void* const* d_in, const int* in_sizes, int n_in,
                              void* d_out, int out_size) {
    (void)in_sizes; (void)n_in; (void)out_size;
    const float* query = (const float*)d_in[0];
    const float* key   = (const float*)d_in[1];
    const float* value = (const float*)d_in[2];
    const int*   mask  = (const int*)d_in[3];
    const float* invsc = (const float*)d_in[4];
    const float* Wq    = (const float*)d_in[5];
    const float* bq    = (const float*)d_in[6];
    const float* Wk    = (const float*)d_in[7];
    const float* bk    = (const float*)d_in[8];
    const float* Wv    = (const float*)d_in[9];
    const float* bv    = (const float*)d_in[10];
    float*       out   = (float*)d_out;

    cudaFuncSetAttribute(proj3_kernel, cudaFuncAttributeMaxDynamicSharedMemorySize,
                         PROJ_SMEM_BYTES);
    proj3_kernel<<<1536, 256, PROJ_SMEM_BYTES>>>(query, key, value,
                                                 Wq, Wk, Wv, bq, bk, bv);

    cudaFuncSetAttribute(attn_mma_kernel, cudaFuncAttributeMaxDynamicSharedMemorySize,
                         ATTN_SMEM_BYTES);
    dim3 ag(S_ / 128, B_ * H_);
    attn_mma_kernel<<<ag, 256, ATTN_SMEM_BYTES>>>(mask, invsc, out);
}